// round 1
// baseline (speedup 1.0000x reference)
#include <cuda_runtime.h>

// Elementwise affine: y = x * 2 + 5 over 8192*8192 fp32.
// Pure HBM streamer: 128-bit vectorized loads/stores, one float4 per thread.
// 8192*8192 = 67108864 floats = 16777216 float4 = 65536 blocks of 256 threads.

__global__ void __launch_bounds__(256) affine_kernel(const float4* __restrict__ x,
                                                     float4* __restrict__ y) {
    unsigned int i = blockIdx.x * 256u + threadIdx.x;
    float4 v = x[i];
    float4 r;
    r.x = fmaf(v.x, 2.0f, 5.0f);
    r.y = fmaf(v.y, 2.0f, 5.0f);
    r.z = fmaf(v.z, 2.0f, 5.0f);
    r.w = fmaf(v.w, 2.0f, 5.0f);
    y[i] = r;
}

extern "C" void kernel_launch(void* const* d_in, const int* in_sizes, int n_in,
                              void* d_out, int out_size) {
    const float4* x = (const float4*)d_in[0];
    float4* y = (float4*)d_out;
    int n = in_sizes[0];          // 67108864
    int n4 = n / 4;               // 16777216
    int blocks = n4 / 256;        // 65536
    affine_kernel<<<blocks, 256>>>(x, y);
}

// round 2
// speedup vs baseline: 1.0027x; 1.0027x over previous
#include <cuda_runtime.h>

// Elementwise affine: y = x * 2 + 5 over 8192*8192 fp32.
// HBM streamer, ILP=2: each thread does two 128-bit loads issued back-to-back
// (MLP_p1=2 -> deeper L1tex/DRAM queues), streaming cache hints (.cs) since
// there is zero reuse.
// 16777216 float4 total; 256 thr/block * 2 float4/thr -> 32768 blocks.

__global__ void __launch_bounds__(256) affine_kernel(const float4* __restrict__ x,
                                                     float4* __restrict__ y) {
    unsigned int base = blockIdx.x * 512u + threadIdx.x;
    unsigned int i0 = base;
    unsigned int i1 = base + 256u;

    // Two independent streaming loads, issued before any use.
    float4 v0 = __ldcs(&x[i0]);
    float4 v1 = __ldcs(&x[i1]);

    float4 r0, r1;
    r0.x = fmaf(v0.x, 2.0f, 5.0f);
    r0.y = fmaf(v0.y, 2.0f, 5.0f);
    r0.z = fmaf(v0.z, 2.0f, 5.0f);
    r0.w = fmaf(v0.w, 2.0f, 5.0f);
    r1.x = fmaf(v1.x, 2.0f, 5.0f);
    r1.y = fmaf(v1.y, 2.0f, 5.0f);
    r1.z = fmaf(v1.z, 2.0f, 5.0f);
    r1.w = fmaf(v1.w, 2.0f, 5.0f);

    __stcs(&y[i0], r0);
    __stcs(&y[i1], r1);
}

extern "C" void kernel_launch(void* const* d_in, const int* in_sizes, int n_in,
                              void* d_out, int out_size) {
    const float4* x = (const float4*)d_in[0];
    float4* y = (float4*)d_out;
    int n = in_sizes[0];            // 67108864
    int n4 = n / 4;                 // 16777216
    int blocks = n4 / 512;          // 32768
    affine_kernel<<<blocks, 256>>>(x, y);
}